// round 5
// baseline (speedup 1.0000x reference)
#include <cuda_runtime.h>
#include <cuda_bf16.h>

// RoIHeads postprocess: softmax -> per-class decode/clip/filter -> per-class NMS -> top-100.
// N=1000 proposals, C=81 classes (80 foreground).
//
// Output layout (float32, 56000 elems), matching flattened+concatenated reference tuple:
//   [0      , 32000) : out_boxes  (80,100,4)
//   [32000  , 40000) : out_scores (80,100)
//   [40000  , 48000) : labels     (80,100)  (cast to float)
//   [48000  , 56000) : out_valid  (80,100)  (0.0/1.0)

#define NPROP 1000
#define NPAD  1024
#define NCLS  80
#define NDET  100

static __device__ float g_scores[NCLS * NPAD];       // class-major, -1 = invalid
static __device__ float g_boxes [NCLS * NPAD * 4];   // class-major decoded+clipped boxes

__global__ void decode_kernel(const float* __restrict__ logits,
                              const float* __restrict__ regs,
                              const float* __restrict__ props) {
    const int n = blockIdx.x;            // proposal
    const int t = threadIdx.x;           // 0..127
    __shared__ float sl[81];
    __shared__ float smax, ssum;

    if (t < 81) sl[t] = logits[n * 81 + t];
    __syncthreads();
    if (t == 0) {
        float m = sl[0];
        #pragma unroll 8
        for (int i = 1; i < 81; i++) m = fmaxf(m, sl[i]);
        smax = m;
    }
    __syncthreads();
    if (t < 81) sl[t] = expf(sl[t] - smax);
    __syncthreads();
    if (t == 0) {
        float s = 0.f;
        #pragma unroll 8
        for (int i = 0; i < 81; i++) s += sl[i];
        ssum = s;
    }
    __syncthreads();

    if (t >= 1 && t <= 80) {
        const float score = sl[t] / ssum;

        const float px1 = props[n * 4 + 0];
        const float py1 = props[n * 4 + 1];
        const float px2 = props[n * 4 + 2];
        const float py2 = props[n * 4 + 3];
        const float w  = px2 - px1;
        const float h  = py2 - py1;
        const float cx = px1 + 0.5f * w;
        const float cy = py1 + 0.5f * h;

        const float* d = regs + n * 324 + t * 4;
        const float BBOX_CLIP = 4.135166556742356f;  // log(1000/16)
        const float dx = d[0] / 10.0f;
        const float dy = d[1] / 10.0f;
        const float dw = fminf(d[2] / 5.0f, BBOX_CLIP);
        const float dh = fminf(d[3] / 5.0f, BBOX_CLIP);

        const float pcx = dx * w + cx;
        const float pcy = dy * h + cy;
        const float pw  = expf(dw) * w;
        const float ph  = expf(dh) * h;

        float x1 = pcx - 0.5f * pw;
        float y1 = pcy - 0.5f * ph;
        float x2 = pcx + 0.5f * pw;
        float y2 = pcy + 0.5f * ph;
        x1 = fminf(fmaxf(x1, 0.f), 800.f);
        y1 = fminf(fmaxf(y1, 0.f), 800.f);
        x2 = fminf(fmaxf(x2, 0.f), 800.f);
        y2 = fminf(fmaxf(y2, 0.f), 800.f);

        const float bw = x2 - x1;
        const float bh = y2 - y1;
        const bool valid = (score >= 0.05f) && (bw >= 1.0f) && (bh >= 1.0f);

        const int idx = (t - 1) * NPAD + n;
        g_scores[idx] = valid ? score : -1.0f;
        g_boxes[idx * 4 + 0] = x1;
        g_boxes[idx * 4 + 1] = y1;
        g_boxes[idx * 4 + 2] = x2;
        g_boxes[idx * 4 + 3] = y2;
    }
}

__global__ __launch_bounds__(512, 1)
void nms_kernel(float* __restrict__ out) {
    const int cls = blockIdx.x;          // 0..79 -> label cls+1
    const int tid = threadIdx.x;         // 0..511

    __shared__ float ss[NPAD];
    __shared__ int   si[NPAD];
    __shared__ float sb[NPROP * 4];
    __shared__ unsigned char supp[NPROP];
    __shared__ int   kept_pos[NDET];
    __shared__ int   s_kept, s_done, s_kc, s_cur;

    const float* gs = g_scores + cls * NPAD;
    const float* gb = g_boxes  + (size_t)cls * NPAD * 4;

    // init sort keys (pad with -2 so pads sort after the -1 "invalid" block)
    #pragma unroll
    for (int i = tid; i < NPAD; i += 512) {
        ss[i] = (i < NPROP) ? gs[i] : -2.0f;
        si[i] = i;
    }
    for (int i = tid; i < NPROP; i += 512) supp[i] = 0;

    // bitonic sort, order: score desc, index asc (strict total order == stable argsort(-s))
    for (int k = 2; k <= NPAD; k <<= 1) {
        for (int j = k >> 1; j > 0; j >>= 1) {
            __syncthreads();
            #pragma unroll
            for (int i = tid; i < NPAD; i += 512) {
                const int ixj = i ^ j;
                if (ixj > i) {
                    const float s1 = ss[i],  s2 = ss[ixj];
                    const int   a  = si[i],  b  = si[ixj];
                    const bool before_ij = (s1 > s2) || (s1 == s2 && a < b);
                    const bool asc = ((i & k) == 0);
                    if (asc ? !before_ij : before_ij) {
                        ss[i] = s2; ss[ixj] = s1;
                        si[i] = b;  si[ixj] = a;
                    }
                }
            }
        }
    }
    __syncthreads();

    // gather boxes into sorted order
    for (int i = tid; i < NPROP; i += 512) {
        const int oi = si[i];
        const float4 bx = *reinterpret_cast<const float4*>(gb + oi * 4);
        sb[i * 4 + 0] = bx.x;
        sb[i * 4 + 1] = bx.y;
        sb[i * 4 + 2] = bx.z;
        sb[i * 4 + 3] = bx.w;
    }
    if (tid == 0) { s_kept = 0; s_cur = 0; }
    __syncthreads();

    // greedy NMS: serial pointer, parallel suppression against each newly kept box
    while (true) {
        if (tid == 0) {
            int c = s_cur;
            while (c < NPROP && supp[c]) c++;
            if (c >= NPROP || ss[c] <= -0.5f || s_kept >= NDET) {
                s_done = 1;
            } else {
                s_done = 0;
                kept_pos[s_kept] = c;
                s_kept++;
                s_cur = c + 1;
                s_kc  = c;
            }
        }
        __syncthreads();
        if (s_done) break;

        const int kc = s_kc;
        const float kx1 = sb[kc * 4 + 0], ky1 = sb[kc * 4 + 1];
        const float kx2 = sb[kc * 4 + 2], ky2 = sb[kc * 4 + 3];
        const float ka  = (kx2 - kx1) * (ky2 - ky1);

        for (int p = kc + 1 + tid; p < NPROP; p += 512) {
            if (!supp[p]) {
                const float x1 = sb[p * 4 + 0], y1 = sb[p * 4 + 1];
                const float x2 = sb[p * 4 + 2], y2 = sb[p * 4 + 3];
                const float iw = fmaxf(0.f, fminf(kx2, x2) - fmaxf(kx1, x1));
                const float ih = fmaxf(0.f, fminf(ky2, y2) - fmaxf(ky1, y1));
                const float inter = iw * ih;
                const float iou = inter / (ka + (x2 - x1) * (y2 - y1) - inter + 1e-9f);
                if (iou > 0.5f) supp[p] = 1;
            }
        }
        __syncthreads();   // make supp visible for thread 0's next scan
    }

    // write outputs (all 100 slots per class; zeros beyond kept count)
    const int M = s_kept;
    for (int k = tid; k < NDET; k += 512) {
        float bx1 = 0.f, by1 = 0.f, bx2 = 0.f, by2 = 0.f, sc = 0.f, lb = 0.f, vl = 0.f;
        if (k < M) {
            const int pos = kept_pos[k];
            bx1 = sb[pos * 4 + 0];
            by1 = sb[pos * 4 + 1];
            bx2 = sb[pos * 4 + 2];
            by2 = sb[pos * 4 + 3];
            sc  = ss[pos];
            lb  = (float)(cls + 1);
            vl  = 1.0f;
        }
        const int slot = cls * NDET + k;
        out[slot * 4 + 0] = bx1;
        out[slot * 4 + 1] = by1;
        out[slot * 4 + 2] = bx2;
        out[slot * 4 + 3] = by2;
        out[32000 + slot] = sc;
        out[40000 + slot] = lb;
        out[48000 + slot] = vl;
    }
}

extern "C" void kernel_launch(void* const* d_in, const int* in_sizes, int n_in,
                              void* d_out, int out_size) {
    // Identify inputs by element count (robust to metadata ordering):
    //   class_logit: 1000*81  = 81000
    //   box_regr:    1000*324 = 324000
    //   proposal:    1000*4   = 4000
    const float* logits = nullptr;
    const float* regs   = nullptr;
    const float* props  = nullptr;
    for (int i = 0; i < n_in; i++) {
        if (in_sizes[i] == 81000)       logits = (const float*)d_in[i];
        else if (in_sizes[i] == 324000) regs   = (const float*)d_in[i];
        else if (in_sizes[i] == 4000)   props  = (const float*)d_in[i];
    }

    decode_kernel<<<NPROP, 128>>>(logits, regs, props);
    nms_kernel<<<NCLS, 512>>>((float*)d_out);
}

// round 10
// speedup vs baseline: 2.6416x; 2.6416x over previous
#include <cuda_runtime.h>
#include <cuda_bf16.h>

// RoIHeads postprocess: softmax -> per-class decode/clip/filter -> per-class NMS -> top-100.
// N=1000 proposals, C=81 classes (80 foreground).
//
// Two kernels:
//   decode: warp-per-proposal shuffle softmax + per-class box decode; writes class-major
//           score (-1 = invalid) and box arrays.
//   nms:    one block per class; ballot-compacts the ~45 valid entries, bitonic-sorts
//           (score desc, orig idx asc), greedy NMS, writes 100 output slots.
//
// Output layout (float32, 56000 elems):
//   [0,32000): boxes (80,100,4)  [32000,40000): scores  [40000,48000): labels  [48000,56000): valid

#define NPROP 1000
#define NPAD  1024
#define NCLS  80
#define NDET  100

static __device__ float  g_scores[NCLS * NPAD];   // class-major; -1 = invalid
static __device__ float4 g_boxes [NCLS * NPAD];   // class-major decoded+clipped boxes

// One warp per proposal. Shuffle-only softmax, then 80 fg class decodes spread over lanes.
__global__ __launch_bounds__(128)
void decode_kernel(const float* __restrict__ logits,
                   const float* __restrict__ regs,
                   const float* __restrict__ props) {
    const int gw   = (blockIdx.x * blockDim.x + threadIdx.x) >> 5;  // proposal
    const int lane = threadIdx.x & 31;
    if (gw >= NPROP) return;

    const float* lg = logits + gw * 81;
    const float v0 = lg[lane];
    const float v1 = lg[lane + 32];
    const float v2 = (lane + 64 < 81) ? lg[lane + 64] : -1e30f;

    float m = fmaxf(fmaxf(v0, v1), v2);
    #pragma unroll
    for (int o = 16; o; o >>= 1) m = fmaxf(m, __shfl_xor_sync(0xffffffffu, m, o));

    float e = expf(v0 - m) + expf(v1 - m) + ((lane + 64 < 81) ? expf(v2 - m) : 0.f);
    #pragma unroll
    for (int o = 16; o; o >>= 1) e += __shfl_xor_sync(0xffffffffu, e, o);

    const float4 pb = *reinterpret_cast<const float4*>(props + gw * 4);
    const float w  = pb.z - pb.x;
    const float h  = pb.w - pb.y;
    const float cx = pb.x + 0.5f * w;
    const float cy = pb.y + 0.5f * h;
    const float* dbase = regs + gw * 324;
    const float BBOX_CLIP = 4.135166556742356f;  // log(1000/16)

    #pragma unroll
    for (int r = 0; r < 3; r++) {
        const int t = lane + 1 + 32 * r;          // fg class id 1..80
        if (t <= 80) {
            const float score = expf(lg[t] - m) / e;

            const float* d = dbase + t * 4;
            const float dx = d[0] / 10.0f;
            const float dy = d[1] / 10.0f;
            const float dw = fminf(d[2] / 5.0f, BBOX_CLIP);
            const float dh = fminf(d[3] / 5.0f, BBOX_CLIP);

            const float pcx = dx * w + cx;
            const float pcy = dy * h + cy;
            const float pw  = expf(dw) * w;
            const float ph  = expf(dh) * h;

            float x1 = fminf(fmaxf(pcx - 0.5f * pw, 0.f), 800.f);
            float y1 = fminf(fmaxf(pcy - 0.5f * ph, 0.f), 800.f);
            float x2 = fminf(fmaxf(pcx + 0.5f * pw, 0.f), 800.f);
            float y2 = fminf(fmaxf(pcy + 0.5f * ph, 0.f), 800.f);

            const bool valid = (score >= 0.05f) && ((x2 - x1) >= 1.0f) && ((y2 - y1) >= 1.0f);
            const int idx = (t - 1) * NPAD + gw;  // class-major
            g_scores[idx] = valid ? score : -1.0f;
            g_boxes[idx]  = make_float4(x1, y1, x2, y2);
        }
    }
}

__global__ __launch_bounds__(128, 1)
void nms_kernel(float* __restrict__ out) {
    const int cls  = blockIdx.x;          // label cls+1
    const int tid  = threadIdx.x;         // 0..127
    const int wid  = tid >> 5;
    const int lane = tid & 31;

    __shared__ float  ss[NPAD];
    __shared__ int    sidx[NPAD];         // original proposal index (ascending within ties)
    __shared__ int    sslot[NPAD];        // compact slot -> box payload pointer
    __shared__ float4 sb_raw[NPAD];       // boxes in compaction order
    __shared__ float4 sb[NPAD];           // boxes in sorted order
    __shared__ unsigned char supp[NPAD];
    __shared__ int kept_pos[NDET];
    __shared__ int warp_cnt[4];
    __shared__ int s_kept, s_done, s_kc, s_cur;

    const float*  gs = g_scores + cls * NPAD;
    const float4* gb = g_boxes  + cls * NPAD;

    // ── ballot compaction of valid entries, preserving original-index order ──
    int base = 0;
    for (int i0 = 0; i0 < NPROP; i0 += 128) {
        const int i = i0 + tid;
        float s = -1.0f;
        float4 b;
        if (i < NPROP) { s = gs[i]; b = gb[i]; }
        const bool v = s > -0.5f;
        const unsigned bal = __ballot_sync(0xffffffffu, v);
        if (lane == 0) warp_cnt[wid] = __popc(bal);
        __syncthreads();
        int woff = 0;
        #pragma unroll
        for (int wv = 0; wv < 4; wv++) if (wv < wid) woff += warp_cnt[wv];
        const int pos = base + woff + __popc(bal & ((1u << lane) - 1u));
        if (v) {
            ss[pos]     = s;
            sidx[pos]   = i;
            sb_raw[pos] = b;
        }
        base += warp_cnt[0] + warp_cnt[1] + warp_cnt[2] + warp_cnt[3];
        __syncthreads();                  // warp_cnt reuse + ss/sb_raw visibility
    }
    const int V = base;

    int P = 2;
    while (P < V) P <<= 1;

    for (int i = tid; i < P; i += 128) {
        if (i >= V) { ss[i] = -2.0f; sidx[i] = 0x7fffffff; }
        sslot[i] = i;
    }
    __syncthreads();

    // ── bitonic sort on (score desc, orig_idx asc): strict total order == stable argsort(-s) ──
    if (P <= 128) {
        // common case (V ~45 -> P = 64): one element per thread
        const int i = tid;
        for (int k = 2; k <= P; k <<= 1) {
            for (int j = k >> 1; j > 0; j >>= 1) {
                if (i < P) {
                    const int ixj = i ^ j;
                    if (ixj > i) {
                        const float s1 = ss[i], s2 = ss[ixj];
                        const int   a = sidx[i], b = sidx[ixj];
                        const bool before = (s1 > s2) || (s1 == s2 && a < b);
                        const bool asc = ((i & k) == 0);
                        if (asc ? !before : before) {
                            ss[i] = s2;  ss[ixj] = s1;
                            sidx[i] = b; sidx[ixj] = a;
                            const int t = sslot[i]; sslot[i] = sslot[ixj]; sslot[ixj] = t;
                        }
                    }
                }
                __syncthreads();
            }
        }
    } else {
        for (int k = 2; k <= P; k <<= 1) {
            for (int j = k >> 1; j > 0; j >>= 1) {
                for (int i = tid; i < P; i += 128) {
                    const int ixj = i ^ j;
                    if (ixj > i) {
                        const float s1 = ss[i], s2 = ss[ixj];
                        const int   a = sidx[i], b = sidx[ixj];
                        const bool before = (s1 > s2) || (s1 == s2 && a < b);
                        const bool asc = ((i & k) == 0);
                        if (asc ? !before : before) {
                            ss[i] = s2;  ss[ixj] = s1;
                            sidx[i] = b; sidx[ixj] = a;
                            const int t = sslot[i]; sslot[i] = sslot[ixj]; sslot[ixj] = t;
                        }
                    }
                }
                __syncthreads();
            }
        }
    }

    // gather boxes into sorted order
    for (int i = tid; i < V; i += 128) {
        sb[i] = sb_raw[sslot[i]];
        supp[i] = 0;
    }
    if (tid == 0) { s_kept = 0; s_cur = 0; }
    __syncthreads();

    // ── greedy NMS (all compacted entries valid; stop at V exhausted or 100 kept) ──
    while (true) {
        if (tid == 0) {
            int c = s_cur;
            while (c < V && supp[c]) c++;
            if (c >= V || s_kept >= NDET) {
                s_done = 1;
            } else {
                s_done = 0;
                kept_pos[s_kept++] = c;
                s_cur = c + 1;
                s_kc  = c;
            }
        }
        __syncthreads();
        if (s_done) break;

        const int kc = s_kc;
        const float4 kb = sb[kc];
        const float ka = (kb.z - kb.x) * (kb.w - kb.y);

        for (int p = kc + 1 + tid; p < V; p += 128) {
            if (!supp[p]) {
                const float4 b = sb[p];
                const float iw = fmaxf(0.f, fminf(kb.z, b.z) - fmaxf(kb.x, b.x));
                const float ih = fmaxf(0.f, fminf(kb.w, b.w) - fmaxf(kb.y, b.y));
                const float inter = iw * ih;
                const float iou = inter / (ka + (b.z - b.x) * (b.w - b.y) - inter + 1e-9f);
                if (iou > 0.5f) supp[p] = 1;
            }
        }
        __syncthreads();
    }

    // ── outputs (all 100 slots per class; zeros beyond kept count) ──
    const int M = s_kept;
    for (int k = tid; k < NDET; k += 128) {
        float4 b = make_float4(0.f, 0.f, 0.f, 0.f);
        float sc = 0.f, lb = 0.f, vl = 0.f;
        if (k < M) {
            const int pos = kept_pos[k];
            b  = sb[pos];
            sc = ss[pos];
            lb = (float)(cls + 1);
            vl = 1.0f;
        }
        const int slot = cls * NDET + k;
        out[slot * 4 + 0] = b.x;
        out[slot * 4 + 1] = b.y;
        out[slot * 4 + 2] = b.z;
        out[slot * 4 + 3] = b.w;
        out[32000 + slot] = sc;
        out[40000 + slot] = lb;
        out[48000 + slot] = vl;
    }
}

extern "C" void kernel_launch(void* const* d_in, const int* in_sizes, int n_in,
                              void* d_out, int out_size) {
    const float* logits = nullptr;
    const float* regs   = nullptr;
    const float* props  = nullptr;
    for (int i = 0; i < n_in; i++) {
        if (in_sizes[i] == 81000)       logits = (const float*)d_in[i];
        else if (in_sizes[i] == 324000) regs   = (const float*)d_in[i];
        else if (in_sizes[i] == 4000)   props  = (const float*)d_in[i];
    }

    decode_kernel<<<(NPROP * 32 + 127) / 128, 128>>>(logits, regs, props);
    nms_kernel<<<NCLS, 128>>>((float*)d_out);
}

// round 12
// speedup vs baseline: 3.8614x; 1.4617x over previous
#include <cuda_runtime.h>
#include <cuda_bf16.h>

// RoIHeads postprocess: softmax -> per-class decode/clip/filter -> per-class NMS -> top-100.
// N=1000 proposals, C=81 classes (80 foreground).
//
// decode: warp-per-proposal shuffle softmax + box decode; writes class-major scores
//         (-1 = invalid) and boxes (boxes only for valid entries).
// nms:    one block per class. Chunk-compact valid entries (~45) with one block scan,
//         bitonic sort (score desc, idx asc), parallel lower-triangular suppression-matrix
//         build, barrier-free kept-mask greedy (suppressed_i = any(kept & row_i), exactly
//         the reference scan), inline output writes.
//
// Output layout (float32, 56000 elems):
//   [0,32000): boxes (80,100,4)  [32000,40000): scores  [40000,48000): labels  [48000,56000): valid

#define NPROP 1000
#define NCLS  80
#define NDET  100

static __device__ float  g_scores[NCLS * NPROP];   // class-major; -1 = invalid
static __device__ float4 g_boxes [NCLS * NPROP];   // written only where valid

__global__ __launch_bounds__(128)
void decode_kernel(const float* __restrict__ logits,
                   const float* __restrict__ regs,
                   const float* __restrict__ props) {
    const int gw   = (blockIdx.x * blockDim.x + threadIdx.x) >> 5;  // proposal
    const int lane = threadIdx.x & 31;
    if (gw >= NPROP) return;

    const float* lg = logits + gw * 81;
    const float v0 = lg[lane];
    const float v1 = lg[lane + 32];
    const float v2 = (lane + 64 < 81) ? lg[lane + 64] : -1e30f;

    float m = fmaxf(fmaxf(v0, v1), v2);
    #pragma unroll
    for (int o = 16; o; o >>= 1) m = fmaxf(m, __shfl_xor_sync(0xffffffffu, m, o));

    float e = expf(v0 - m) + expf(v1 - m) + ((lane + 64 < 81) ? expf(v2 - m) : 0.f);
    #pragma unroll
    for (int o = 16; o; o >>= 1) e += __shfl_xor_sync(0xffffffffu, e, o);

    const float4 pb = *reinterpret_cast<const float4*>(props + gw * 4);
    const float w  = pb.z - pb.x;
    const float h  = pb.w - pb.y;
    const float cx = pb.x + 0.5f * w;
    const float cy = pb.y + 0.5f * h;
    const float* dbase = regs + gw * 324;
    const float BBOX_CLIP = 4.135166556742356f;  // log(1000/16)

    #pragma unroll
    for (int r = 0; r < 3; r++) {
        const int t = lane + 1 + 32 * r;          // fg class id 1..80
        if (t <= 80) {
            const float score = expf(lg[t] - m) / e;

            const float* d = dbase + t * 4;
            const float dx = d[0] / 10.0f;
            const float dy = d[1] / 10.0f;
            const float dw = fminf(d[2] / 5.0f, BBOX_CLIP);
            const float dh = fminf(d[3] / 5.0f, BBOX_CLIP);

            const float pcx = dx * w + cx;
            const float pcy = dy * h + cy;
            const float pw  = expf(dw) * w;
            const float ph  = expf(dh) * h;

            float x1 = fminf(fmaxf(pcx - 0.5f * pw, 0.f), 800.f);
            float y1 = fminf(fmaxf(pcy - 0.5f * ph, 0.f), 800.f);
            float x2 = fminf(fmaxf(pcx + 0.5f * pw, 0.f), 800.f);
            float y2 = fminf(fmaxf(pcy + 0.5f * ph, 0.f), 800.f);

            const bool valid = (score >= 0.05f) && ((x2 - x1) >= 1.0f) && ((y2 - y1) >= 1.0f);
            const int idx = (t - 1) * NPROP + gw;
            g_scores[idx] = valid ? score : -1.0f;
            if (valid) g_boxes[idx] = make_float4(x1, y1, x2, y2);
        }
    }
}

__device__ __forceinline__ float iou_f(float4 a, float aa, float4 b) {
    const float iw = fmaxf(0.f, fminf(a.z, b.z) - fmaxf(a.x, b.x));
    const float ih = fmaxf(0.f, fminf(a.w, b.w) - fmaxf(a.y, b.y));
    const float inter = iw * ih;
    const float ab = (b.z - b.x) * (b.w - b.y);
    return inter / (aa + ab - inter + 1e-9f);
}

__global__ __launch_bounds__(128, 1)
void nms_kernel(float* __restrict__ out) {
    const int cls  = blockIdx.x;
    const int tid  = threadIdx.x;
    const int wid  = tid >> 5;
    const int lane = tid & 31;

    __shared__ float  ss[1024];
    __shared__ int    sidx[1024];
    __shared__ float4 sb[1024];
    __shared__ int    wsum[4];
    // fallback-only state (V > 128)
    __shared__ unsigned char supp[1024];
    __shared__ int kept_pos[NDET];
    __shared__ int s_kept, s_done, s_kc, s_cur;
    // fast-path suppression matrix (V <= 128): row i has bit j set iff j<i and IoU(i,j)>0.5
    __shared__ unsigned smask[128][4];

    const float*  gs = g_scores + cls * NPROP;
    const float4* gb = g_boxes  + cls * NPROP;

    // ── compaction: thread t owns chunk [t*8, t*8+8) ──
    int cnt = 0;
    if (tid < 125) {
        #pragma unroll
        for (int j = 0; j < 8; j++) cnt += (gs[tid * 8 + j] > -0.5f) ? 1 : 0;
    }
    // block exclusive scan (thread order == ascending index order)
    int x = cnt;
    #pragma unroll
    for (int o = 1; o < 32; o <<= 1) {
        const int y = __shfl_up_sync(0xffffffffu, x, o);
        if (lane >= o) x += y;
    }
    if (lane == 31) wsum[wid] = x;
    __syncthreads();
    int woff = 0;
    #pragma unroll
    for (int wv = 0; wv < 4; wv++) if (wv < wid) woff += wsum[wv];
    const int V = wsum[0] + wsum[1] + wsum[2] + wsum[3];

    int wp = woff + x - cnt;
    if (tid < 125) {
        #pragma unroll
        for (int j = 0; j < 8; j++) {
            const float s = gs[tid * 8 + j];    // L1-hot second pass
            if (s > -0.5f) { ss[wp] = s; sidx[wp] = tid * 8 + j; wp++; }
        }
    }

    int P = 2;
    while (P < V) P <<= 1;
    __syncthreads();
    for (int i = V + tid; i < P; i += 128) { ss[i] = -2.0f; sidx[i] = 0x7fffffff; }
    __syncthreads();

    // ── bitonic sort on (score desc, idx asc): strict total order == stable argsort(-s) ──
    for (int k = 2; k <= P; k <<= 1) {
        for (int j = k >> 1; j > 0; j >>= 1) {
            for (int i = tid; i < P; i += 128) {
                const int ixj = i ^ j;
                if (ixj > i) {
                    const float s1 = ss[i], s2 = ss[ixj];
                    const int   a = sidx[i], b = sidx[ixj];
                    const bool before = (s1 > s2) || (s1 == s2 && a < b);
                    const bool asc = ((i & k) == 0);
                    if (asc ? !before : before) {
                        ss[i] = s2;  ss[ixj] = s1;
                        sidx[i] = b; sidx[ixj] = a;
                    }
                }
            }
            __syncthreads();
        }
    }

    // gather boxes in sorted order (only V entries, from L2)
    for (int i = tid; i < V; i += 128) sb[i] = gb[sidx[i]];
    __syncthreads();

    if (V <= 128) {
        // ── fast path: parallel suppression-matrix build, one barrier ──
        if (tid < V) {
            const int row = tid;
            const float4 bi = sb[row];
            const float ai = (bi.z - bi.x) * (bi.w - bi.y);
            unsigned m0 = 0, m1 = 0, m2 = 0, m3 = 0;
            for (int j = 0; j < row; j++) {
                const unsigned bit = (iou_f(bi, ai, sb[j]) > 0.5f) ? (1u << (j & 31)) : 0u;
                if      (j < 32) m0 |= bit;
                else if (j < 64) m1 |= bit;
                else if (j < 96) m2 |= bit;
                else             m3 |= bit;
            }
            smask[row][0] = m0; smask[row][1] = m1;
            smask[row][2] = m2; smask[row][3] = m3;
        }
        __syncthreads();

        // ── barrier-free kept-mask greedy (all threads redundant, identical state):
        //    suppressed(c) = smask[c] intersects kept_mask  — exactly the reference scan.
        unsigned k0 = 0, k1 = 0, k2 = 0, k3 = 0;
        int m = 0;
        for (int c = 0; c < V && m < NDET; c++) {
            unsigned sup = smask[c][0] & k0;
            if (c >= 32) sup |= smask[c][1] & k1;
            if (c >= 64) sup |= smask[c][2] & k2;
            if (c >= 96) sup |= smask[c][3] & k3;
            if (!sup) {
                if (tid == m) {
                    const float4 b = sb[c];
                    const int slot = cls * NDET + m;
                    out[slot * 4 + 0] = b.x;
                    out[slot * 4 + 1] = b.y;
                    out[slot * 4 + 2] = b.z;
                    out[slot * 4 + 3] = b.w;
                    out[32000 + slot] = ss[c];
                    out[40000 + slot] = (float)(cls + 1);
                    out[48000 + slot] = 1.0f;
                }
                if      (c < 32) k0 |= 1u << c;
                else if (c < 64) k1 |= 1u << (c - 32);
                else if (c < 96) k2 |= 1u << (c - 64);
                else             k3 |= 1u << (c - 96);
                m++;
            }
        }
        // zero-fill remaining slots
        if (tid >= m && tid < NDET) {
            const int slot = cls * NDET + tid;
            out[slot * 4 + 0] = 0.f;
            out[slot * 4 + 1] = 0.f;
            out[slot * 4 + 2] = 0.f;
            out[slot * 4 + 3] = 0.f;
            out[32000 + slot] = 0.f;
            out[40000 + slot] = 0.f;
            out[48000 + slot] = 0.f;
        }
    } else {
        // ── fallback (V > 128, statistically never taken; correctness only) ──
        for (int i = tid; i < V; i += 128) supp[i] = 0;
        if (tid == 0) { s_kept = 0; s_cur = 0; }
        __syncthreads();
        while (true) {
            if (tid == 0) {
                int c = s_cur;
                while (c < V && supp[c]) c++;
                if (c >= V || s_kept >= NDET) s_done = 1;
                else { s_done = 0; kept_pos[s_kept++] = c; s_cur = c + 1; s_kc = c; }
            }
            __syncthreads();
            if (s_done) break;
            const int kc = s_kc;
            const float4 kb = sb[kc];
            const float ka = (kb.z - kb.x) * (kb.w - kb.y);
            for (int p = kc + 1 + tid; p < V; p += 128)
                if (!supp[p] && iou_f(kb, ka, sb[p]) > 0.5f) supp[p] = 1;
            __syncthreads();
        }
        const int M = s_kept;
        for (int k = tid; k < NDET; k += 128) {
            float4 b = make_float4(0.f, 0.f, 0.f, 0.f);
            float sc = 0.f, lb = 0.f, vl = 0.f;
            if (k < M) {
                const int pos = kept_pos[k];
                b = sb[pos]; sc = ss[pos]; lb = (float)(cls + 1); vl = 1.0f;
            }
            const int slot = cls * NDET + k;
            out[slot * 4 + 0] = b.x;
            out[slot * 4 + 1] = b.y;
            out[slot * 4 + 2] = b.z;
            out[slot * 4 + 3] = b.w;
            out[32000 + slot] = sc;
            out[40000 + slot] = lb;
            out[48000 + slot] = vl;
        }
    }
}

extern "C" void kernel_launch(void* const* d_in, const int* in_sizes, int n_in,
                              void* d_out, int out_size) {
    const float* logits = nullptr;
    const float* regs   = nullptr;
    const float* props  = nullptr;
    for (int i = 0; i < n_in; i++) {
        if (in_sizes[i] == 81000)       logits = (const float*)d_in[i];
        else if (in_sizes[i] == 324000) regs   = (const float*)d_in[i];
        else if (in_sizes[i] == 4000)   props  = (const float*)d_in[i];
    }

    decode_kernel<<<(NPROP * 32 + 127) / 128, 128>>>(logits, regs, props);
    nms_kernel<<<NCLS, 128>>>((float*)d_out);
}

// round 13
// speedup vs baseline: 4.0935x; 1.0601x over previous
#include <cuda_runtime.h>
#include <cuda_bf16.h>

// RoIHeads postprocess: softmax -> per-class decode/clip/filter -> per-class NMS -> top-100.
// N=1000 proposals, C=81 classes (80 foreground).
//
// decode: warp-per-proposal shuffle softmax + box decode; class-major scores (-1 invalid),
//         boxes written only where valid.
// nms:    one block per class. Register compaction + block scan (2 barriers), barrier-free
//         rank-sort into sorted arrays (1 barrier), parallel lower-triangular suppression
//         matrix (1 barrier), barrier-free kept-mask greedy, inline output writes.
//         V>128 falls back to bitonic sort + serial greedy (statistically never taken).
//
// Output layout (float32, 56000 elems):
//   [0,32000): boxes (80,100,4)  [32000,40000): scores  [40000,48000): labels  [48000,56000): valid

#define NPROP 1000
#define NCLS  80
#define NDET  100
#define VMAX  128

static __device__ float  g_scores[NCLS * NPROP];   // class-major; -1 = invalid
static __device__ float4 g_boxes [NCLS * NPROP];   // written only where valid

__global__ __launch_bounds__(128)
void decode_kernel(const float* __restrict__ logits,
                   const float* __restrict__ regs,
                   const float* __restrict__ props) {
    const int gw   = (blockIdx.x * blockDim.x + threadIdx.x) >> 5;  // proposal
    const int lane = threadIdx.x & 31;
    if (gw >= NPROP) return;

    const float* lg = logits + gw * 81;
    const float v0 = lg[lane];
    const float v1 = lg[lane + 32];
    const float v2 = (lane + 64 < 81) ? lg[lane + 64] : -1e30f;

    float m = fmaxf(fmaxf(v0, v1), v2);
    #pragma unroll
    for (int o = 16; o; o >>= 1) m = fmaxf(m, __shfl_xor_sync(0xffffffffu, m, o));

    float e = expf(v0 - m) + expf(v1 - m) + ((lane + 64 < 81) ? expf(v2 - m) : 0.f);
    #pragma unroll
    for (int o = 16; o; o >>= 1) e += __shfl_xor_sync(0xffffffffu, e, o);

    const float4 pb = *reinterpret_cast<const float4*>(props + gw * 4);
    const float w  = pb.z - pb.x;
    const float h  = pb.w - pb.y;
    const float cx = pb.x + 0.5f * w;
    const float cy = pb.y + 0.5f * h;
    const float* dbase = regs + gw * 324;
    const float BBOX_CLIP = 4.135166556742356f;  // log(1000/16)

    #pragma unroll
    for (int r = 0; r < 3; r++) {
        const int t = lane + 1 + 32 * r;          // fg class id 1..80
        if (t <= 80) {
            const float score = expf(lg[t] - m) / e;

            const float* d = dbase + t * 4;
            const float dx = d[0] / 10.0f;
            const float dy = d[1] / 10.0f;
            const float dw = fminf(d[2] / 5.0f, BBOX_CLIP);
            const float dh = fminf(d[3] / 5.0f, BBOX_CLIP);

            const float pcx = dx * w + cx;
            const float pcy = dy * h + cy;
            const float pw  = expf(dw) * w;
            const float ph  = expf(dh) * h;

            float x1 = fminf(fmaxf(pcx - 0.5f * pw, 0.f), 800.f);
            float y1 = fminf(fmaxf(pcy - 0.5f * ph, 0.f), 800.f);
            float x2 = fminf(fmaxf(pcx + 0.5f * pw, 0.f), 800.f);
            float y2 = fminf(fmaxf(pcy + 0.5f * ph, 0.f), 800.f);

            const bool valid = (score >= 0.05f) && ((x2 - x1) >= 1.0f) && ((y2 - y1) >= 1.0f);
            const int idx = (t - 1) * NPROP + gw;
            g_scores[idx] = valid ? score : -1.0f;
            if (valid) g_boxes[idx] = make_float4(x1, y1, x2, y2);
        }
    }
}

__device__ __forceinline__ float iou_f(float4 a, float aa, float4 b) {
    const float iw = fmaxf(0.f, fminf(a.z, b.z) - fmaxf(a.x, b.x));
    const float ih = fmaxf(0.f, fminf(a.w, b.w) - fmaxf(a.y, b.y));
    const float inter = iw * ih;
    const float ab = (b.z - b.x) * (b.w - b.y);
    return inter / (aa + ab - inter + 1e-9f);
}

__global__ __launch_bounds__(128, 1)
void nms_kernel(float* __restrict__ out) {
    const int cls  = blockIdx.x;
    const int tid  = threadIdx.x;
    const int wid  = tid >> 5;
    const int lane = tid & 31;

    __shared__ float  ss[1024];          // compacted (unsorted) scores; fallback sort space
    __shared__ int    sidx[1024];        // compacted (unsorted) orig indices
    __shared__ float  ss_s[VMAX];        // fast path: sorted scores
    __shared__ float4 sb_s[VMAX];        // fast path: sorted boxes
    __shared__ unsigned smask[VMAX][4];  // row i: bit j set iff j<i and IoU(i,j)>0.5
    __shared__ int    wsum[4];
    // fallback-only (V > 128)
    __shared__ float4 sb[1024];
    __shared__ unsigned char supp[1024];
    __shared__ int kept_pos[NDET];
    __shared__ int s_kept, s_done, s_kc, s_cur;

    const float*  gs = g_scores + cls * NPROP;
    const float4* gb = g_boxes  + cls * NPROP;

    // ── compaction: thread t owns chunk [t*8, t*8+8), kept in registers ──
    float v[8];
    int cnt = 0;
    if (tid < 125) {
        const float4 a = *reinterpret_cast<const float4*>(gs + tid * 8);
        const float4 b = *reinterpret_cast<const float4*>(gs + tid * 8 + 4);
        v[0] = a.x; v[1] = a.y; v[2] = a.z; v[3] = a.w;
        v[4] = b.x; v[5] = b.y; v[6] = b.z; v[7] = b.w;
        #pragma unroll
        for (int j = 0; j < 8; j++) cnt += (v[j] > -0.5f) ? 1 : 0;
    }
    // block exclusive scan (thread order == ascending index order)
    int x = cnt;
    #pragma unroll
    for (int o = 1; o < 32; o <<= 1) {
        const int y = __shfl_up_sync(0xffffffffu, x, o);
        if (lane >= o) x += y;
    }
    if (lane == 31) wsum[wid] = x;
    __syncthreads();
    int woff = 0;
    #pragma unroll
    for (int wv = 0; wv < 4; wv++) if (wv < wid) woff += wsum[wv];
    const int V = wsum[0] + wsum[1] + wsum[2] + wsum[3];

    int wp = woff + x - cnt;
    if (tid < 125) {
        #pragma unroll
        for (int j = 0; j < 8; j++) {
            if (v[j] > -0.5f) { ss[wp] = v[j]; sidx[wp] = tid * 8 + j; wp++; }
        }
    }
    __syncthreads();

    if (V <= VMAX) {
        // ── barrier-free rank sort: thread i computes its rank under (score desc, idx asc) ──
        if (tid < V) {
            const float si = ss[tid];
            const int   ii = sidx[tid];
            int r = 0;
            for (int j = 0; j < V; j++) {
                const float sj = ss[j];
                const int   ij = sidx[j];
                r += ((sj > si) || (sj == si && ij < ii)) ? 1 : 0;
            }
            ss_s[r] = si;
            sb_s[r] = gb[ii];            // gather straight into sorted slot (one L2 trip)
        }
        __syncthreads();

        // ── parallel suppression-matrix build (one barrier) ──
        if (tid < V) {
            const int row = tid;
            const float4 bi = sb_s[row];
            const float ai = (bi.z - bi.x) * (bi.w - bi.y);
            unsigned m0 = 0, m1 = 0, m2 = 0, m3 = 0;
            for (int j = 0; j < row; j++) {
                const unsigned bit = (iou_f(bi, ai, sb_s[j]) > 0.5f) ? (1u << (j & 31)) : 0u;
                if      (j < 32) m0 |= bit;
                else if (j < 64) m1 |= bit;
                else if (j < 96) m2 |= bit;
                else             m3 |= bit;
            }
            smask[row][0] = m0; smask[row][1] = m1;
            smask[row][2] = m2; smask[row][3] = m3;
        }
        __syncthreads();

        // ── barrier-free kept-mask greedy (all threads redundant, identical state):
        //    suppressed(c) = smask[c] intersects kept_mask  — exactly the reference scan.
        unsigned k0 = 0, k1 = 0, k2 = 0, k3 = 0;
        int m = 0;
        for (int c = 0; c < V && m < NDET; c++) {
            unsigned sup = smask[c][0] & k0;
            if (c >= 32) sup |= smask[c][1] & k1;
            if (c >= 64) sup |= smask[c][2] & k2;
            if (c >= 96) sup |= smask[c][3] & k3;
            if (!sup) {
                if (tid == m) {
                    const float4 b = sb_s[c];
                    const int slot = cls * NDET + m;
                    out[slot * 4 + 0] = b.x;
                    out[slot * 4 + 1] = b.y;
                    out[slot * 4 + 2] = b.z;
                    out[slot * 4 + 3] = b.w;
                    out[32000 + slot] = ss_s[c];
                    out[40000 + slot] = (float)(cls + 1);
                    out[48000 + slot] = 1.0f;
                }
                if      (c < 32) k0 |= 1u << c;
                else if (c < 64) k1 |= 1u << (c - 32);
                else if (c < 96) k2 |= 1u << (c - 64);
                else             k3 |= 1u << (c - 96);
                m++;
            }
        }
        // zero-fill remaining slots
        if (tid >= m && tid < NDET) {
            const int slot = cls * NDET + tid;
            out[slot * 4 + 0] = 0.f;
            out[slot * 4 + 1] = 0.f;
            out[slot * 4 + 2] = 0.f;
            out[slot * 4 + 3] = 0.f;
            out[32000 + slot] = 0.f;
            out[40000 + slot] = 0.f;
            out[48000 + slot] = 0.f;
        }
    } else {
        // ── fallback (V > 128, statistically never taken; correctness only) ──
        int P = 2;
        while (P < V) P <<= 1;
        for (int i = V + tid; i < P; i += 128) { ss[i] = -2.0f; sidx[i] = 0x7fffffff; }
        __syncthreads();
        for (int k = 2; k <= P; k <<= 1) {
            for (int j = k >> 1; j > 0; j >>= 1) {
                for (int i = tid; i < P; i += 128) {
                    const int ixj = i ^ j;
                    if (ixj > i) {
                        const float s1 = ss[i], s2 = ss[ixj];
                        const int   a = sidx[i], b = sidx[ixj];
                        const bool before = (s1 > s2) || (s1 == s2 && a < b);
                        const bool asc = ((i & k) == 0);
                        if (asc ? !before : before) {
                            ss[i] = s2;  ss[ixj] = s1;
                            sidx[i] = b; sidx[ixj] = a;
                        }
                    }
                }
                __syncthreads();
            }
        }
        for (int i = tid; i < V; i += 128) { sb[i] = gb[sidx[i]]; supp[i] = 0; }
        if (tid == 0) { s_kept = 0; s_cur = 0; }
        __syncthreads();
        while (true) {
            if (tid == 0) {
                int c = s_cur;
                while (c < V && supp[c]) c++;
                if (c >= V || s_kept >= NDET) s_done = 1;
                else { s_done = 0; kept_pos[s_kept++] = c; s_cur = c + 1; s_kc = c; }
            }
            __syncthreads();
            if (s_done) break;
            const int kc = s_kc;
            const float4 kb = sb[kc];
            const float ka = (kb.z - kb.x) * (kb.w - kb.y);
            for (int p = kc + 1 + tid; p < V; p += 128)
                if (!supp[p] && iou_f(kb, ka, sb[p]) > 0.5f) supp[p] = 1;
            __syncthreads();
        }
        const int M = s_kept;
        for (int k = tid; k < NDET; k += 128) {
            float4 b = make_float4(0.f, 0.f, 0.f, 0.f);
            float sc = 0.f, lb = 0.f, vl = 0.f;
            if (k < M) {
                const int pos = kept_pos[k];
                b = sb[pos]; sc = ss[pos]; lb = (float)(cls + 1); vl = 1.0f;
            }
            const int slot = cls * NDET + k;
            out[slot * 4 + 0] = b.x;
            out[slot * 4 + 1] = b.y;
            out[slot * 4 + 2] = b.z;
            out[slot * 4 + 3] = b.w;
            out[32000 + slot] = sc;
            out[40000 + slot] = lb;
            out[48000 + slot] = vl;
        }
    }
}

extern "C" void kernel_launch(void* const* d_in, const int* in_sizes, int n_in,
                              void* d_out, int out_size) {
    const float* logits = nullptr;
    const float* regs   = nullptr;
    const float* props  = nullptr;
    for (int i = 0; i < n_in; i++) {
        if (in_sizes[i] == 81000)       logits = (const float*)d_in[i];
        else if (in_sizes[i] == 324000) regs   = (const float*)d_in[i];
        else if (in_sizes[i] == 4000)   props  = (const float*)d_in[i];
    }

    decode_kernel<<<(NPROP * 32 + 127) / 128, 128>>>(logits, regs, props);
    nms_kernel<<<NCLS, 128>>>((float*)d_out);
}

// round 15
// speedup vs baseline: 5.0829x; 1.2417x over previous
#include <cuda_runtime.h>
#include <cuda_bf16.h>

// RoIHeads postprocess: softmax -> per-class decode/clip/filter -> per-class NMS -> top-100.
// N=1000 proposals, C=81 classes (80 foreground).
//
// decode: warp-per-proposal shuffle softmax + box decode; class-major scores (-1 invalid),
//         boxes written only where valid.
// nms:    one block (256 thr) per class. float4 compaction into packed 64-bit keys
//         (score bits << 32 | ~idx  ==  (score desc, idx asc) total order), barrier-free
//         rank-sort, split-row suppression-matrix build (2 threads/row + atomicOr),
//         barrier-free kept-mask greedy (exactly the reference scan), inline outputs.
//         V>128 falls back to bitonic-on-keys + serial greedy (statistically never taken).
//
// Output layout (float32, 56000 elems):
//   [0,32000): boxes (80,100,4)  [32000,40000): scores  [40000,48000): labels  [48000,56000): valid

#define NPROP 1000
#define NCLS  80
#define NDET  100
#define VMAX  128
#define TB    256

static __device__ float  g_scores[NCLS * NPROP];   // class-major; -1 = invalid
static __device__ float4 g_boxes [NCLS * NPROP];   // written only where valid

__global__ __launch_bounds__(128)
void decode_kernel(const float* __restrict__ logits,
                   const float* __restrict__ regs,
                   const float* __restrict__ props) {
    const int gw   = (blockIdx.x * blockDim.x + threadIdx.x) >> 5;  // proposal
    const int lane = threadIdx.x & 31;
    if (gw >= NPROP) return;

    const float* lg = logits + gw * 81;
    const float v0 = lg[lane];
    const float v1 = lg[lane + 32];
    const float v2 = (lane + 64 < 81) ? lg[lane + 64] : -1e30f;

    float m = fmaxf(fmaxf(v0, v1), v2);
    #pragma unroll
    for (int o = 16; o; o >>= 1) m = fmaxf(m, __shfl_xor_sync(0xffffffffu, m, o));

    float e = expf(v0 - m) + expf(v1 - m) + ((lane + 64 < 81) ? expf(v2 - m) : 0.f);
    #pragma unroll
    for (int o = 16; o; o >>= 1) e += __shfl_xor_sync(0xffffffffu, e, o);

    const float4 pb = *reinterpret_cast<const float4*>(props + gw * 4);
    const float w  = pb.z - pb.x;
    const float h  = pb.w - pb.y;
    const float cx = pb.x + 0.5f * w;
    const float cy = pb.y + 0.5f * h;
    const float* dbase = regs + gw * 324;
    const float BBOX_CLIP = 4.135166556742356f;  // log(1000/16)

    #pragma unroll
    for (int r = 0; r < 3; r++) {
        const int t = lane + 1 + 32 * r;          // fg class id 1..80
        if (t <= 80) {
            const float score = expf(lg[t] - m) / e;

            const float* d = dbase + t * 4;
            const float dx = d[0] / 10.0f;
            const float dy = d[1] / 10.0f;
            const float dw = fminf(d[2] / 5.0f, BBOX_CLIP);
            const float dh = fminf(d[3] / 5.0f, BBOX_CLIP);

            const float pcx = dx * w + cx;
            const float pcy = dy * h + cy;
            const float pw  = expf(dw) * w;
            const float ph  = expf(dh) * h;

            float x1 = fminf(fmaxf(pcx - 0.5f * pw, 0.f), 800.f);
            float y1 = fminf(fmaxf(pcy - 0.5f * ph, 0.f), 800.f);
            float x2 = fminf(fmaxf(pcx + 0.5f * pw, 0.f), 800.f);
            float y2 = fminf(fmaxf(pcy + 0.5f * ph, 0.f), 800.f);

            const bool valid = (score >= 0.05f) && ((x2 - x1) >= 1.0f) && ((y2 - y1) >= 1.0f);
            const int idx = (t - 1) * NPROP + gw;
            g_scores[idx] = valid ? score : -1.0f;
            if (valid) g_boxes[idx] = make_float4(x1, y1, x2, y2);
        }
    }
}

__device__ __forceinline__ float iou_f(float4 a, float aa, float4 b) {
    const float iw = fmaxf(0.f, fminf(a.z, b.z) - fmaxf(a.x, b.x));
    const float ih = fmaxf(0.f, fminf(a.w, b.w) - fmaxf(a.y, b.y));
    const float inter = iw * ih;
    const float ab = (b.z - b.x) * (b.w - b.y);
    return inter / (aa + ab - inter + 1e-9f);
}

__global__ __launch_bounds__(TB, 1)
void nms_kernel(float* __restrict__ out) {
    const int cls  = blockIdx.x;
    const int tid  = threadIdx.x;
    const int wid  = tid >> 5;
    const int lane = tid & 31;

    __shared__ unsigned long long skey[1024];   // packed keys, compacted (index order)
    __shared__ float  ss_s[VMAX];               // fast path: sorted scores
    __shared__ float4 sb_s[VMAX];               // fast path: sorted boxes
    __shared__ uint4  smask[VMAX];              // row i: bit j set iff j<i and IoU(i,j)>0.5
    __shared__ int    wsum[8];
    // fallback-only (V > 128)
    __shared__ float4 sbf[1024];
    __shared__ unsigned char supp[1024];
    __shared__ int kept_pos[NDET];
    __shared__ int s_kept, s_done, s_kc, s_cur;

    const float*  gs = g_scores + cls * NPROP;
    const float4* gb = g_boxes  + cls * NPROP;

    // ── compaction: thread t owns [4t, 4t+4), one float4 load ──
    float v[4];
    int cnt = 0;
    if (tid < 250) {
        const float4 a = *reinterpret_cast<const float4*>(gs + tid * 4);
        v[0] = a.x; v[1] = a.y; v[2] = a.z; v[3] = a.w;
        #pragma unroll
        for (int j = 0; j < 4; j++) cnt += (v[j] > -0.5f) ? 1 : 0;
    }
    // block exclusive scan (thread order == ascending index order)
    int x = cnt;
    #pragma unroll
    for (int o = 1; o < 32; o <<= 1) {
        const int y = __shfl_up_sync(0xffffffffu, x, o);
        if (lane >= o) x += y;
    }
    if (lane == 31) wsum[wid] = x;
    __syncthreads();
    int woff = 0;
    #pragma unroll
    for (int wv = 0; wv < 8; wv++) if (wv < wid) woff += wsum[wv];
    const int V = wsum[0] + wsum[1] + wsum[2] + wsum[3]
                + wsum[4] + wsum[5] + wsum[6] + wsum[7];

    int wp = woff + x - cnt;
    if (tid < 250) {
        #pragma unroll
        for (int j = 0; j < 4; j++) {
            if (v[j] > -0.5f) {
                // key: score bits high (desc), ~idx low (idx asc). strict total order.
                skey[wp++] = ((unsigned long long)__float_as_uint(v[j]) << 32)
                           | (unsigned)(~(tid * 4 + j));
            }
        }
    }
    __syncthreads();

    if (V <= VMAX) {
        // ── barrier-free rank sort on packed keys; gather straight into sorted slots ──
        if (tid < V) {
            const unsigned long long k = skey[tid];
            int r = 0;
            #pragma unroll 4
            for (int j = 0; j < V; j++) r += (skey[j] > k) ? 1 : 0;
            ss_s[r] = __uint_as_float((unsigned)(k >> 32));
            sb_s[r] = gb[~(unsigned)k];
            smask[r] = make_uint4(0u, 0u, 0u, 0u);   // r is a permutation of [0,V)
        }
        __syncthreads();

        // ── suppression matrix, 2 threads per row: t<128 -> j in [0,row/2), else [row/2,row) ──
        {
            const int row = tid & 127;
            if (row > 0 && row < V) {
                const int j0 = (tid < 128) ? 0 : (row >> 1);
                const int j1 = (tid < 128) ? (row >> 1) : row;
                const float4 bi = sb_s[row];
                const float  ai = (bi.z - bi.x) * (bi.w - bi.y);
                unsigned m0 = 0, m1 = 0, m2 = 0, m3 = 0;
                #pragma unroll 4
                for (int j = j0; j < j1; j++) {
                    const unsigned bit = (iou_f(bi, ai, sb_s[j]) > 0.5f) ? (1u << (j & 31)) : 0u;
                    if      (j < 32) m0 |= bit;
                    else if (j < 64) m1 |= bit;
                    else if (j < 96) m2 |= bit;
                    else             m3 |= bit;
                }
                unsigned* mp = reinterpret_cast<unsigned*>(&smask[row]);
                if (m0) atomicOr(mp + 0, m0);
                if (m1) atomicOr(mp + 1, m1);
                if (m2) atomicOr(mp + 2, m2);
                if (m3) atomicOr(mp + 3, m3);
            }
        }
        __syncthreads();

        // ── barrier-free kept-mask greedy (all threads redundant, identical state):
        //    suppressed(c) = smask[c] intersects kept_mask  — exactly the reference scan.
        unsigned k0 = 0, k1 = 0, k2 = 0, k3 = 0;
        int m = 0;
        #pragma unroll 4
        for (int c = 0; c < V; c++) {
            if (m >= NDET) break;
            const uint4 w = smask[c];                 // one LDS.128
            unsigned sup = w.x & k0;
            if (c >= 32) sup |= w.y & k1;
            if (c >= 64) sup |= w.z & k2;
            if (c >= 96) sup |= w.w & k3;
            if (!sup) {
                if (tid == m) {
                    const float4 b = sb_s[c];
                    const int slot = cls * NDET + m;
                    out[slot * 4 + 0] = b.x;
                    out[slot * 4 + 1] = b.y;
                    out[slot * 4 + 2] = b.z;
                    out[slot * 4 + 3] = b.w;
                    out[32000 + slot] = ss_s[c];
                    out[40000 + slot] = (float)(cls + 1);
                    out[48000 + slot] = 1.0f;
                }
                if      (c < 32) k0 |= 1u << c;
                else if (c < 64) k1 |= 1u << (c - 32);
                else if (c < 96) k2 |= 1u << (c - 64);
                else             k3 |= 1u << (c - 96);
                m++;
            }
        }
        // zero-fill remaining slots
        if (tid >= m && tid < NDET) {
            const int slot = cls * NDET + tid;
            out[slot * 4 + 0] = 0.f;
            out[slot * 4 + 1] = 0.f;
            out[slot * 4 + 2] = 0.f;
            out[slot * 4 + 3] = 0.f;
            out[32000 + slot] = 0.f;
            out[40000 + slot] = 0.f;
            out[48000 + slot] = 0.f;
        }
    } else {
        // ── fallback (V > 128, statistically never taken; correctness only) ──
        int P = 2;
        while (P < V) P <<= 1;
        for (int i = V + tid; i < P; i += TB) skey[i] = 0ull;   // pads sort last
        __syncthreads();
        // bitonic sort, descending by key
        for (int k = 2; k <= P; k <<= 1) {
            for (int j = k >> 1; j > 0; j >>= 1) {
                for (int i = tid; i < P; i += TB) {
                    const int ixj = i ^ j;
                    if (ixj > i) {
                        const unsigned long long a = skey[i], b = skey[ixj];
                        const bool before = (a > b);
                        const bool asc = ((i & k) == 0);
                        if (asc ? !before : before) { skey[i] = b; skey[ixj] = a; }
                    }
                }
                __syncthreads();
            }
        }
        for (int i = tid; i < V; i += TB) {
            sbf[i] = gb[~(unsigned)skey[i]];
            supp[i] = 0;
        }
        if (tid == 0) { s_kept = 0; s_cur = 0; }
        __syncthreads();
        while (true) {
            if (tid == 0) {
                int c = s_cur;
                while (c < V && supp[c]) c++;
                if (c >= V || s_kept >= NDET) s_done = 1;
                else { s_done = 0; kept_pos[s_kept++] = c; s_cur = c + 1; s_kc = c; }
            }
            __syncthreads();
            if (s_done) break;
            const int kc = s_kc;
            const float4 kb = sbf[kc];
            const float ka = (kb.z - kb.x) * (kb.w - kb.y);
            for (int p = kc + 1 + tid; p < V; p += TB)
                if (!supp[p] && iou_f(kb, ka, sbf[p]) > 0.5f) supp[p] = 1;
            __syncthreads();
        }
        const int M = s_kept;
        for (int k = tid; k < NDET; k += TB) {
            float4 b = make_float4(0.f, 0.f, 0.f, 0.f);
            float sc = 0.f, lb = 0.f, vl = 0.f;
            if (k < M) {
                const int pos = kept_pos[k];
                b  = sbf[pos];
                sc = __uint_as_float((unsigned)(skey[pos] >> 32));
                lb = (float)(cls + 1);
                vl = 1.0f;
            }
            const int slot = cls * NDET + k;
            out[slot * 4 + 0] = b.x;
            out[slot * 4 + 1] = b.y;
            out[slot * 4 + 2] = b.z;
            out[slot * 4 + 3] = b.w;
            out[32000 + slot] = sc;
            out[40000 + slot] = lb;
            out[48000 + slot] = vl;
        }
    }
}

extern "C" void kernel_launch(void* const* d_in, const int* in_sizes, int n_in,
                              void* d_out, int out_size) {
    const float* logits = nullptr;
    const float* regs   = nullptr;
    const float* props  = nullptr;
    for (int i = 0; i < n_in; i++) {
        if (in_sizes[i] == 81000)       logits = (const float*)d_in[i];
        else if (in_sizes[i] == 324000) regs   = (const float*)d_in[i];
        else if (in_sizes[i] == 4000)   props  = (const float*)d_in[i];
    }

    decode_kernel<<<(NPROP * 32 + 127) / 128, 128>>>(logits, regs, props);
    nms_kernel<<<NCLS, TB>>>((float*)d_out);
}

// round 16
// speedup vs baseline: 10.7519x; 2.1153x over previous
#include <cuda_runtime.h>
#include <cuda_bf16.h>

// RoIHeads postprocess: softmax -> per-class decode/clip/filter -> per-class NMS -> top-100.
// N=1000 proposals, C=81 classes (80 foreground).
//
// decode: warp-per-proposal shuffle softmax + box decode; class-major scores (-1 invalid),
//         boxes written only where valid.
// nms:    one block (256 thr) per class. float4 compaction into packed 64-bit keys
//         (score bits << 32 | ~idx == (score desc, idx asc) total order), barrier-free
//         rank-sort, division-free suppression matrix (2 threads/row + atomicOr,
//         IoU>0.5 <=> 3*inter > ai+aj+1e-9), sparse greedy over nonzero rows only,
//         branchless nth-set-bit output. V>128 bitonic fallback (never taken).
//
// Output layout (float32, 56000 elems):
//   [0,32000): boxes (80,100,4)  [32000,40000): scores  [40000,48000): labels  [48000,56000): valid

#define NPROP 1000
#define NCLS  80
#define NDET  100
#define VMAX  128
#define TB    256

static __device__ float  g_scores[NCLS * NPROP];   // class-major; -1 = invalid
static __device__ float4 g_boxes [NCLS * NPROP];   // written only where valid

__global__ __launch_bounds__(128)
void decode_kernel(const float* __restrict__ logits,
                   const float* __restrict__ regs,
                   const float* __restrict__ props) {
    const int gw   = (blockIdx.x * blockDim.x + threadIdx.x) >> 5;  // proposal
    const int lane = threadIdx.x & 31;
    if (gw >= NPROP) return;

    const float* lg = logits + gw * 81;
    const float v0 = lg[lane];
    const float v1 = lg[lane + 32];
    const float v2 = (lane + 64 < 81) ? lg[lane + 64] : -1e30f;

    float m = fmaxf(fmaxf(v0, v1), v2);
    #pragma unroll
    for (int o = 16; o; o >>= 1) m = fmaxf(m, __shfl_xor_sync(0xffffffffu, m, o));

    float e = expf(v0 - m) + expf(v1 - m) + ((lane + 64 < 81) ? expf(v2 - m) : 0.f);
    #pragma unroll
    for (int o = 16; o; o >>= 1) e += __shfl_xor_sync(0xffffffffu, e, o);
    const float inv_e = 1.0f / e;

    const float4 pb = *reinterpret_cast<const float4*>(props + gw * 4);
    const float w  = pb.z - pb.x;
    const float h  = pb.w - pb.y;
    const float cx = pb.x + 0.5f * w;
    const float cy = pb.y + 0.5f * h;
    const float* dbase = regs + gw * 324;
    const float BBOX_CLIP = 4.135166556742356f;  // log(1000/16)

    #pragma unroll
    for (int r = 0; r < 3; r++) {
        const int t = lane + 1 + 32 * r;          // fg class id 1..80
        if (t <= 80) {
            const float score = expf(lg[t] - m) * inv_e;

            const float* d = dbase + t * 4;
            const float dx = d[0] * 0.1f;
            const float dy = d[1] * 0.1f;
            const float dw = fminf(d[2] * 0.2f, BBOX_CLIP);
            const float dh = fminf(d[3] * 0.2f, BBOX_CLIP);

            const float pcx = dx * w + cx;
            const float pcy = dy * h + cy;
            const float pw  = expf(dw) * w;
            const float ph  = expf(dh) * h;

            float x1 = fminf(fmaxf(pcx - 0.5f * pw, 0.f), 800.f);
            float y1 = fminf(fmaxf(pcy - 0.5f * ph, 0.f), 800.f);
            float x2 = fminf(fmaxf(pcx + 0.5f * pw, 0.f), 800.f);
            float y2 = fminf(fmaxf(pcy + 0.5f * ph, 0.f), 800.f);

            const bool valid = (score >= 0.05f) && ((x2 - x1) >= 1.0f) && ((y2 - y1) >= 1.0f);
            const int idx = (t - 1) * NPROP + gw;
            g_scores[idx] = valid ? score : -1.0f;
            if (valid) g_boxes[idx] = make_float4(x1, y1, x2, y2);
        }
    }
}

__device__ __forceinline__ unsigned mask_n(int n) {   // n low bits set, clamped [0,32]
    return (n <= 0) ? 0u : ((n >= 32) ? 0xffffffffu : ((1u << n) - 1u));
}

__global__ __launch_bounds__(TB, 1)
void nms_kernel(float* __restrict__ out) {
    const int cls  = blockIdx.x;
    const int tid  = threadIdx.x;
    const int wid  = tid >> 5;
    const int lane = tid & 31;

    __shared__ unsigned long long skey[1024];   // packed keys, compacted (index order)
    __shared__ float  ss_s[VMAX];               // sorted scores
    __shared__ float  sarea[VMAX];              // sorted box areas
    __shared__ float4 sb_s[VMAX];               // sorted boxes
    __shared__ uint4  smask[VMAX];              // row i: bit j set iff j<i and IoU(i,j)>0.5
    __shared__ unsigned nzw[4];                 // nonzero-row bitmask
    __shared__ int    wsum[8];
    // fallback-only (V > 128)
    __shared__ float4 sbf[1024];
    __shared__ unsigned char supp[1024];
    __shared__ int kept_pos[NDET];
    __shared__ int s_kept, s_done, s_kc, s_cur;

    const float*  gs = g_scores + cls * NPROP;
    const float4* gb = g_boxes  + cls * NPROP;

    // ── compaction: thread t owns [4t, 4t+4), one float4 load ──
    float v[4];
    int cnt = 0;
    if (tid < 250) {
        const float4 a = *reinterpret_cast<const float4*>(gs + tid * 4);
        v[0] = a.x; v[1] = a.y; v[2] = a.z; v[3] = a.w;
        #pragma unroll
        for (int j = 0; j < 4; j++) cnt += (v[j] > -0.5f) ? 1 : 0;
    }
    int x = cnt;
    #pragma unroll
    for (int o = 1; o < 32; o <<= 1) {
        const int y = __shfl_up_sync(0xffffffffu, x, o);
        if (lane >= o) x += y;
    }
    if (lane == 31) wsum[wid] = x;
    __syncthreads();
    int woff = 0;
    #pragma unroll
    for (int wv = 0; wv < 8; wv++) if (wv < wid) woff += wsum[wv];
    const int V = wsum[0] + wsum[1] + wsum[2] + wsum[3]
                + wsum[4] + wsum[5] + wsum[6] + wsum[7];

    int wp = woff + x - cnt;
    if (tid < 250) {
        #pragma unroll
        for (int j = 0; j < 4; j++) {
            if (v[j] > -0.5f) {
                skey[wp++] = ((unsigned long long)__float_as_uint(v[j]) << 32)
                           | (unsigned)(~(tid * 4 + j));
            }
        }
    }
    __syncthreads();

    if (V <= VMAX) {
        // ── barrier-free rank sort on packed keys; gather straight into sorted slots ──
        if (tid < V) {
            const unsigned long long k = skey[tid];
            int r = 0;
            #pragma unroll 4
            for (int j = 0; j < V; j++) r += (skey[j] > k) ? 1 : 0;
            const float4 b = gb[~(unsigned)k];
            ss_s[r]  = __uint_as_float((unsigned)(k >> 32));
            sb_s[r]  = b;
            sarea[r] = (b.z - b.x) * (b.w - b.y);
            smask[r] = make_uint4(0u, 0u, 0u, 0u);   // r is a permutation of [0,V)
        }
        __syncthreads();

        // ── division-free suppression matrix, 2 threads/row ──
        {
            const int row = tid & 127;
            if (row > 0 && row < V) {
                const int j0 = (tid < 128) ? 0 : (row >> 1);
                const int j1 = (tid < 128) ? (row >> 1) : row;
                const float4 bi = sb_s[row];
                const float  ai = sarea[row];
                unsigned m0 = 0, m1 = 0, m2 = 0, m3 = 0;
                #pragma unroll 4
                for (int j = j0; j < j1; j++) {
                    const float4 bj = sb_s[j];
                    const float iw = fmaxf(0.f, fminf(bi.z, bj.z) - fmaxf(bi.x, bj.x));
                    const float ih = fmaxf(0.f, fminf(bi.w, bj.w) - fmaxf(bi.y, bj.y));
                    const float inter = iw * ih;
                    // IoU > 0.5  <=>  3*inter > ai + aj + 1e-9   (denominator > 0)
                    const unsigned bit = (3.0f * inter > ai + sarea[j] + 1e-9f)
                                         ? (1u << (j & 31)) : 0u;
                    if      (j < 32) m0 |= bit;
                    else if (j < 64) m1 |= bit;
                    else if (j < 96) m2 |= bit;
                    else             m3 |= bit;
                }
                unsigned* mp = reinterpret_cast<unsigned*>(&smask[row]);
                if (m0) atomicOr(mp + 0, m0);
                if (m1) atomicOr(mp + 1, m1);
                if (m2) atomicOr(mp + 2, m2);
                if (m3) atomicOr(mp + 3, m3);
            }
        }
        __syncthreads();

        // ── collect nonzero rows (suppression is rare: typically ~5-15 rows) ──
        if (tid < 128) {
            bool nz = (tid > 0) && (tid < V);
            if (nz) {
                const uint4 w = smask[tid];
                nz = (w.x | w.y | w.z | w.w) != 0u;
            }
            const unsigned b = __ballot_sync(0xffffffffu, nz);
            if (lane == 0) nzw[wid] = b;
        }
        __syncthreads();

        // ── sparse greedy (uniform, redundant on all threads):
        //    kept starts all-valid; fix up only nonzero rows in ascending order.
        //    Exactly the reference scan: zero rows are final immediately; when row c is
        //    processed, all bits < c (zero rows + earlier nonzero rows) are final.
        unsigned k0 = mask_n(V), k1 = mask_n(V - 32), k2 = mask_n(V - 64), k3 = mask_n(V - 96);
        #pragma unroll
        for (int wI = 0; wI < 4; wI++) {
            unsigned nz = nzw[wI];
            while (nz) {
                const int b = __ffs(nz) - 1;
                nz &= nz - 1;
                const int c = (wI << 5) + b;
                const uint4 wm = smask[c];
                const unsigned sup = (wm.x & k0) | (wm.y & k1) | (wm.z & k2) | (wm.w & k3);
                if (sup) {
                    const unsigned clr = ~(1u << b);
                    if      (wI == 0) k0 &= clr;
                    else if (wI == 1) k1 &= clr;
                    else if (wI == 2) k2 &= clr;
                    else              k3 &= clr;
                }
            }
        }

        // ── branchless output: thread t writes the t-th kept detection (or zeros) ──
        if (tid < NDET) {
            const int c0 = __popc(k0), c1 = __popc(k1), c2 = __popc(k2), c3 = __popc(k3);
            int M = c0 + c1 + c2 + c3;
            if (M > NDET) M = NDET;

            float4 b = make_float4(0.f, 0.f, 0.f, 0.f);
            float sc = 0.f, lb = 0.f, vl = 0.f;
            if (tid < M) {
                int t = tid;
                const int p01 = c0, p02 = c0 + c1, p03 = c0 + c1 + c2;
                unsigned w; int base;
                if      (t < p01) { w = k0; base = 0;  }
                else if (t < p02) { w = k1; base = 32; t -= p01; }
                else if (t < p03) { w = k2; base = 64; t -= p02; }
                else              { w = k3; base = 96; t -= p03; }
                // t-th (0-based) set bit of w via popc binary search (predicable)
                int pos = 0;
                int cc = __popc(w & 0xFFFFu);
                if (t >= cc) { t -= cc; pos += 16; w >>= 16; }
                cc = __popc(w & 0xFFu);
                if (t >= cc) { t -= cc; pos += 8;  w >>= 8;  }
                cc = __popc(w & 0xFu);
                if (t >= cc) { t -= cc; pos += 4;  w >>= 4;  }
                cc = __popc(w & 0x3u);
                if (t >= cc) { t -= cc; pos += 2;  w >>= 2;  }
                cc = (int)(w & 1u);
                if (t >= cc) { pos += 1; }
                const int c = base + pos;
                b  = sb_s[c];
                sc = ss_s[c];
                lb = (float)(cls + 1);
                vl = 1.0f;
            }
            const int slot = cls * NDET + tid;
            out[slot * 4 + 0] = b.x;
            out[slot * 4 + 1] = b.y;
            out[slot * 4 + 2] = b.z;
            out[slot * 4 + 3] = b.w;
            out[32000 + slot] = sc;
            out[40000 + slot] = lb;
            out[48000 + slot] = vl;
        }
    } else {
        // ── fallback (V > 128, statistically never taken; correctness only) ──
        int P = 2;
        while (P < V) P <<= 1;
        for (int i = V + tid; i < P; i += TB) skey[i] = 0ull;
        __syncthreads();
        for (int k = 2; k <= P; k <<= 1) {
            for (int j = k >> 1; j > 0; j >>= 1) {
                for (int i = tid; i < P; i += TB) {
                    const int ixj = i ^ j;
                    if (ixj > i) {
                        const unsigned long long a = skey[i], b = skey[ixj];
                        const bool before = (a > b);
                        const bool asc = ((i & k) == 0);
                        if (asc ? !before : before) { skey[i] = b; skey[ixj] = a; }
                    }
                }
                __syncthreads();
            }
        }
        for (int i = tid; i < V; i += TB) {
            sbf[i] = gb[~(unsigned)skey[i]];
            supp[i] = 0;
        }
        if (tid == 0) { s_kept = 0; s_cur = 0; }
        __syncthreads();
        while (true) {
            if (tid == 0) {
                int c = s_cur;
                while (c < V && supp[c]) c++;
                if (c >= V || s_kept >= NDET) s_done = 1;
                else { s_done = 0; kept_pos[s_kept++] = c; s_cur = c + 1; s_kc = c; }
            }
            __syncthreads();
            if (s_done) break;
            const int kc = s_kc;
            const float4 kb = sbf[kc];
            const float ka = (kb.z - kb.x) * (kb.w - kb.y);
            for (int p = kc + 1 + tid; p < V; p += TB) {
                if (!supp[p]) {
                    const float4 bb = sbf[p];
                    const float iw = fmaxf(0.f, fminf(kb.z, bb.z) - fmaxf(kb.x, bb.x));
                    const float ih = fmaxf(0.f, fminf(kb.w, bb.w) - fmaxf(kb.y, bb.y));
                    const float inter = iw * ih;
                    const float ab = (bb.z - bb.x) * (bb.w - bb.y);
                    if (3.0f * inter > ka + ab + 1e-9f) supp[p] = 1;
                }
            }
            __syncthreads();
        }
        const int M = s_kept;
        for (int k = tid; k < NDET; k += TB) {
            float4 b = make_float4(0.f, 0.f, 0.f, 0.f);
            float sc = 0.f, lb = 0.f, vl = 0.f;
            if (k < M) {
                const int pos = kept_pos[k];
                b  = sbf[pos];
                sc = __uint_as_float((unsigned)(skey[pos] >> 32));
                lb = (float)(cls + 1);
                vl = 1.0f;
            }
            const int slot = cls * NDET + k;
            out[slot * 4 + 0] = b.x;
            out[slot * 4 + 1] = b.y;
            out[slot * 4 + 2] = b.z;
            out[slot * 4 + 3] = b.w;
            out[32000 + slot] = sc;
            out[40000 + slot] = lb;
            out[48000 + slot] = vl;
        }
    }
}

extern "C" void kernel_launch(void* const* d_in, const int* in_sizes, int n_in,
                              void* d_out, int out_size) {
    const float* logits = nullptr;
    const float* regs   = nullptr;
    const float* props  = nullptr;
    for (int i = 0; i < n_in; i++) {
        if (in_sizes[i] == 81000)       logits = (const float*)d_in[i];
        else if (in_sizes[i] == 324000) regs   = (const float*)d_in[i];
        else if (in_sizes[i] == 4000)   props  = (const float*)d_in[i];
    }

    decode_kernel<<<(NPROP * 32 + 127) / 128, 128>>>(logits, regs, props);
    nms_kernel<<<NCLS, TB>>>((float*)d_out);
}